// round 3
// baseline (speedup 1.0000x reference)
#include <cuda_runtime.h>
#include <float.h>

#define DDIM   64
#define KCODES 512
#define KC     128     // codes per chunk
#define RB     128     // rows per block
#define NROWS  65536

// -------- output layout (reference tuple, raveled, concatenated, float32) ----
#define OFF_Q    0            // quantize_st          64*32*32*64 = 4194304
#define OFF_DIFF 4194304      // diff (scalar)        1
#define OFF_IND  4194305      // embed_ind            65536
#define OFF_EN   4259841      // embed_new            64*512 = 32768
#define OFF_NCS  4292609      // new_cluster_size     512
#define OFF_NEA  4293121      // new_embed_avg        32768
// total = 4325889

// -------- device scratch (no allocations allowed) ---------------------------
__device__ float  g_esum[DDIM * KCODES];
__device__ float  g_cnt[KCODES];
__device__ float  g_e2[KCODES];
__device__ double g_diff;

// ============================================================================
// Kernel 0: zero scratch + precompute ||e_k||^2
// ============================================================================
__global__ void init_kernel(const float* __restrict__ embed) {
    int t = blockIdx.x * blockDim.x + threadIdx.x;
    if (t < DDIM * KCODES) g_esum[t] = 0.0f;
    if (t < KCODES) {
        g_cnt[t] = 0.0f;
        float s = 0.0f;
        #pragma unroll 8
        for (int d = 0; d < DDIM; d++) {
            float e = embed[d * KCODES + t];
            s = fmaf(e, e, s);
        }
        g_e2[t] = s;
    }
    if (t == 0) g_diff = 0.0;
}

// ============================================================================
// Kernel 1: distances + argmin + quantize/scatter epilogue
//   block tile: 128 rows x (4 chunks of 128 codes)
//   thread tile: 8 rows x 8 codes, d-dimension packed into f32x2 lanes
// ============================================================================
__global__ __launch_bounds__(256) void vq_main(const float* __restrict__ input,
                                               const float* __restrict__ embed,
                                               float* __restrict__ out) {
    __shared__ float  As[RB * DDIM];          // [row][d]   32 KB
    __shared__ float2 Bs[(DDIM / 2) * KC];    // [d2][k]    32 KB (d even/odd pairs)
    __shared__ float  sE2[KC];
    __shared__ float  sMin[RB];
    __shared__ int    sIdx[RB];

    const int tid = threadIdx.x;
    const int r0  = blockIdx.x * RB;

    // ---- load A tile (direct coalesced copy, row-major) ----
    {
        const float4* src = (const float4*)(input + (size_t)r0 * DDIM);
        float4*       dst = (float4*)As;
        #pragma unroll
        for (int i = 0; i < 8; i++) dst[tid + 256 * i] = src[tid + 256 * i];
    }
    if (tid < RB) { sMin[tid] = FLT_MAX; sIdx[tid] = 0; }

    const int tx = tid & 15;   // code group  (codes tx + 16*j)
    const int ty = tid >> 4;   // row group   (rows  ty + 16*i)

    for (int kc = 0; kc < KCODES; kc += KC) {
        __syncthreads();   // previous readers of Bs done / As store visible
        // ---- load B chunk into d-pair layout: Bs[d2][k] = {e[2d2][k], e[2d2+1][k]} ----
        #pragma unroll
        for (int i = 0; i < 16; i++) {
            int idx = tid + 256 * i;
            int d2 = idx >> 7, k = idx & 127;
            Bs[idx] = make_float2(embed[(2 * d2)     * KCODES + kc + k],
                                  embed[(2 * d2 + 1) * KCODES + kc + k]);
        }
        if (tid < KC) sE2[tid] = g_e2[kc + tid];
        __syncthreads();

        // ---- 8x8 microkernel, d packed in f32x2 ----
        unsigned long long acc[8][8];
        #pragma unroll
        for (int i = 0; i < 8; i++)
            #pragma unroll
            for (int j = 0; j < 8; j++) acc[i][j] = 0ull;

        const unsigned long long* Bsu = (const unsigned long long*)Bs;
        #pragma unroll 8
        for (int d2 = 0; d2 < DDIM / 2; d2++) {
            unsigned long long a2[8], b2[8];
            #pragma unroll
            for (int i = 0; i < 8; i++)
                a2[i] = *(const unsigned long long*)&As[(ty + 16 * i) * DDIM + 2 * d2];
            #pragma unroll
            for (int j = 0; j < 8; j++)
                b2[j] = Bsu[d2 * KC + tx + 16 * j];
            #pragma unroll
            for (int i = 0; i < 8; i++)
                #pragma unroll
                for (int j = 0; j < 8; j++)
                    asm("fma.rn.f32x2 %0, %1, %2, %0;"
                        : "+l"(acc[i][j]) : "l"(a2[i]), "l"(b2[j]));
        }

        // ---- per-row argmin over this chunk (first-index tie break) ----
        #pragma unroll
        for (int i = 0; i < 8; i++) {
            float bv = FLT_MAX;
            int   bk = 0x7fffffff;
            #pragma unroll
            for (int j = 0; j < 8; j++) {
                int kk = tx + 16 * j;
                float dot = __uint_as_float((unsigned)acc[i][j]) +
                            __uint_as_float((unsigned)(acc[i][j] >> 32));
                float dist = sE2[kk] - 2.0f * dot;   // ||x||^2 constant per row, omitted
                int kg = kc + kk;
                if (dist < bv || (dist == bv && kg < bk)) { bv = dist; bk = kg; }
            }
            // reduce across 16 tx lanes (xor <=8 never crosses 16-lane halves)
            #pragma unroll
            for (int off = 8; off; off >>= 1) {
                float ov = __shfl_xor_sync(0xffffffffu, bv, off);
                int   ok = __shfl_xor_sync(0xffffffffu, bk, off);
                if (ov < bv || (ov == bv && ok < bk)) { bv = ov; bk = ok; }
            }
            if (tx == 0) {
                int row = ty + 16 * i;      // this thread owns this row across chunks
                if (bv < sMin[row] || (bv == sMin[row] && bk < sIdx[row])) {
                    sMin[row] = bv; sIdx[row] = bk;
                }
            }
        }
    }
    __syncthreads();

    // ---- epilogue: quantize_st, index out, scatter, diff ----
    const int warp = tid >> 5, lane = tid & 31;
    double dsum = 0.0;
    for (int row = warp; row < RB; row += 8) {
        int kbest = sIdx[row];
        int gr = r0 + row;
        if (lane == 0) {
            out[OFF_IND + gr] = (float)kbest;
            atomicAdd(&g_cnt[kbest], 1.0f);
        }
        #pragma unroll
        for (int h = 0; h < 2; h++) {
            int d = lane + 32 * h;
            float x = As[row * DDIM + d];
            float q = embed[d * KCODES + kbest];
            out[OFF_Q + (size_t)gr * DDIM + d] = x + (q - x);  // ref op order
            float df = q - x;
            dsum += (double)df * (double)df;
            atomicAdd(&g_esum[d * KCODES + kbest], x);
        }
    }
    #pragma unroll
    for (int off = 16; off; off >>= 1)
        dsum += __shfl_xor_sync(0xffffffffu, dsum, off);
    if (lane == 0) atomicAdd(&g_diff, dsum);
}

// ============================================================================
// Kernel 2: EMA update + normalize + diff mean
// ============================================================================
__global__ void vq_finalize(const float* __restrict__ cluster_size,
                            const float* __restrict__ embed_avg,
                            float* __restrict__ out) {
    __shared__ float red[512];
    const int k = threadIdx.x;
    const float DEC = 0.99f;
    const float OMD = (float)(1.0 - 0.99);   // match python 1.0-DECAY rounding

    float ncs = cluster_size[k] * DEC + OMD * g_cnt[k];
    out[OFF_NCS + k] = ncs;
    red[k] = ncs;
    __syncthreads();
    for (int s = 256; s; s >>= 1) {
        if (k < s) red[k] += red[k + s];
        __syncthreads();
    }
    float n  = red[0];
    float cs = (ncs + 1e-5f) / (n + 512.0f * 1e-5f) * n;

    for (int d = 0; d < DDIM; d++) {
        int idx = d * KCODES + k;               // coalesced across k
        float nea = embed_avg[idx] * DEC + OMD * g_esum[idx];
        out[OFF_NEA + idx] = nea;
        out[OFF_EN  + idx] = nea / cs;
    }
    if (k == 0) out[OFF_DIFF] = (float)(g_diff * (1.0 / 4194304.0));
}

// ============================================================================
extern "C" void kernel_launch(void* const* d_in, const int* in_sizes, int n_in,
                              void* d_out, int out_size) {
    const float* input        = (const float*)d_in[0];
    const float* embed        = (const float*)d_in[1];
    const float* cluster_size = (const float*)d_in[2];
    const float* embed_avg    = (const float*)d_in[3];
    float* out = (float*)d_out;

    init_kernel<<<128, 256>>>(embed);
    vq_main<<<512, 256>>>(input, embed, out);
    vq_finalize<<<1, 512>>>(cluster_size, embed_avg, out);
}

// round 7
// speedup vs baseline: 1.2298x; 1.2298x over previous
#include <cuda_runtime.h>
#include <float.h>

#define DDIM   64
#define KCODES 512
#define KC     128     // codes per chunk
#define RB     64      // rows per block
#define NROWS  65536

// -------- output layout (reference tuple, raveled, concatenated, float32) ----
#define OFF_Q    0            // quantize_st          64*32*32*64 = 4194304
#define OFF_DIFF 4194304      // diff (scalar)        1
#define OFF_IND  4194305      // embed_ind            65536
#define OFF_EN   4259841      // embed_new            64*512 = 32768
#define OFF_NCS  4292609      // new_cluster_size     512
#define OFF_NEA  4293121      // new_embed_avg        32768
// total = 4325889

// -------- device scratch (no allocations allowed) ---------------------------
__device__ float  g_esum[DDIM * KCODES];
__device__ float  g_cnt[KCODES];
__device__ double g_diff;

// ============================================================================
// Kernel 0: zero scratch only (e2 moved into vq_main)
// ============================================================================
__global__ void init_kernel() {
    int t = blockIdx.x * blockDim.x + threadIdx.x;
    if (t < DDIM * KCODES) g_esum[t] = 0.0f;
    if (t < KCODES) g_cnt[t] = 0.0f;
    if (t == 0) g_diff = 0.0;
}

// ============================================================================
// Kernel 1: distances + argmin + quantize/scatter epilogue
//   block tile: 64 rows x (4 chunks of 128 codes)
//   thread tile: 4 rows x 8 codes, d-dimension packed into f32x2 lanes
//   2 CTAs/SM (regs <= 128), 1024 CTAs
// ============================================================================
__global__ __launch_bounds__(256, 2) void vq_main(const float* __restrict__ input,
                                                  const float* __restrict__ embed,
                                                  float* __restrict__ out) {
    __shared__ float  As[RB * DDIM];          // [row][d]   16 KB
    __shared__ float2 Bs[(DDIM / 2) * KC];    // [d2][k]    32 KB (d even/odd pairs)
    __shared__ float  sE2[KC];
    __shared__ float  sMin[RB];
    __shared__ int    sIdx[RB];

    const int tid = threadIdx.x;
    const int r0  = blockIdx.x * RB;

    // ---- load A tile (direct coalesced copy, row-major) ----
    {
        const float4* src = (const float4*)(input + (size_t)r0 * DDIM);
        float4*       dst = (float4*)As;
        #pragma unroll
        for (int i = 0; i < 4; i++) dst[tid + 256 * i] = src[tid + 256 * i];
    }
    if (tid < RB) { sMin[tid] = FLT_MAX; sIdx[tid] = 0; }

    const int tx = tid & 15;   // code group  (codes tx + 16*j)
    const int ty = tid >> 4;   // row group   (rows  ty + 16*i, i<4)

    for (int kc = 0; kc < KCODES; kc += KC) {
        __syncthreads();   // previous readers of Bs/sE2 done / As store visible
        // ---- load B chunk into d-pair layout: Bs[d2][k] = {e[2d2][k], e[2d2+1][k]} ----
        #pragma unroll
        for (int i = 0; i < 16; i++) {
            int idx = tid + 256 * i;
            int d2 = idx >> 7, k = idx & 127;
            Bs[idx] = make_float2(embed[(2 * d2)     * KCODES + kc + k],
                                  embed[(2 * d2 + 1) * KCODES + kc + k]);
        }
        __syncthreads();

        // ---- sE2 for this chunk from the smem tile (threads 0..127) ----
        if (tid < KC) {
            float s = 0.0f;
            #pragma unroll 8
            for (int d2 = 0; d2 < DDIM / 2; d2++) {
                float2 e = Bs[d2 * KC + tid];
                s = fmaf(e.x, e.x, fmaf(e.y, e.y, s));
            }
            sE2[tid] = s;
        }

        // ---- 4x8 microkernel, d packed in f32x2 ----
        unsigned long long acc[4][8];
        #pragma unroll
        for (int i = 0; i < 4; i++)
            #pragma unroll
            for (int j = 0; j < 8; j++) acc[i][j] = 0ull;

        const unsigned long long* Bsu = (const unsigned long long*)Bs;
        #pragma unroll 8
        for (int d2 = 0; d2 < DDIM / 2; d2++) {
            unsigned long long a2[4], b2[8];
            #pragma unroll
            for (int i = 0; i < 4; i++)
                a2[i] = *(const unsigned long long*)&As[(ty + 16 * i) * DDIM + 2 * d2];
            #pragma unroll
            for (int j = 0; j < 8; j++)
                b2[j] = Bsu[d2 * KC + tx + 16 * j];
            #pragma unroll
            for (int i = 0; i < 4; i++)
                #pragma unroll
                for (int j = 0; j < 8; j++)
                    asm("fma.rn.f32x2 %0, %1, %2, %0;"
                        : "+l"(acc[i][j]) : "l"(a2[i]), "l"(b2[j]));
        }
        __syncthreads();   // sE2 writes visible to all readers below

        // ---- per-row argmin over this chunk (first-index tie break) ----
        #pragma unroll
        for (int i = 0; i < 4; i++) {
            float bv = FLT_MAX;
            int   bk = 0x7fffffff;
            #pragma unroll
            for (int j = 0; j < 8; j++) {
                int kk = tx + 16 * j;
                float dot = __uint_as_float((unsigned)acc[i][j]) +
                            __uint_as_float((unsigned)(acc[i][j] >> 32));
                float dist = sE2[kk] - 2.0f * dot;   // ||x||^2 constant per row, omitted
                int kg = kc + kk;
                if (dist < bv || (dist == bv && kg < bk)) { bv = dist; bk = kg; }
            }
            // reduce across 16 tx lanes (xor <=8 never crosses 16-lane halves)
            #pragma unroll
            for (int off = 8; off; off >>= 1) {
                float ov = __shfl_xor_sync(0xffffffffu, bv, off);
                int   ok = __shfl_xor_sync(0xffffffffu, bk, off);
                if (ov < bv || (ov == bv && ok < bk)) { bv = ov; bk = ok; }
            }
            if (tx == 0) {
                int row = ty + 16 * i;      // this thread owns this row across chunks
                if (bv < sMin[row] || (bv == sMin[row] && bk < sIdx[row])) {
                    sMin[row] = bv; sIdx[row] = bk;
                }
            }
        }
    }
    __syncthreads();

    // ---- epilogue: quantize_st, index out, scatter, diff ----
    const int warp = tid >> 5, lane = tid & 31;
    double dsum = 0.0;
    for (int row = warp; row < RB; row += 8) {
        int kbest = sIdx[row];
        int gr = r0 + row;
        if (lane == 0) {
            out[OFF_IND + gr] = (float)kbest;
            atomicAdd(&g_cnt[kbest], 1.0f);
        }
        #pragma unroll
        for (int h = 0; h < 2; h++) {
            int d = lane + 32 * h;
            float x = As[row * DDIM + d];
            float q = embed[d * KCODES + kbest];
            out[OFF_Q + (size_t)gr * DDIM + d] = x + (q - x);  // ref op order
            float df = q - x;
            dsum += (double)df * (double)df;
            atomicAdd(&g_esum[d * KCODES + kbest], x);
        }
    }
    #pragma unroll
    for (int off = 16; off; off >>= 1)
        dsum += __shfl_xor_sync(0xffffffffu, dsum, off);
    if (lane == 0) atomicAdd(&g_diff, dsum);
}

// ============================================================================
// Kernel 2: EMA update + normalize + diff mean
// ============================================================================
__global__ void vq_finalize(const float* __restrict__ cluster_size,
                            const float* __restrict__ embed_avg,
                            float* __restrict__ out) {
    __shared__ float red[512];
    const int k = threadIdx.x;
    const float DEC = 0.99f;
    const float OMD = (float)(1.0 - 0.99);   // match python 1.0-DECAY rounding

    float ncs = cluster_size[k] * DEC + OMD * g_cnt[k];
    out[OFF_NCS + k] = ncs;
    red[k] = ncs;
    __syncthreads();
    for (int s = 256; s; s >>= 1) {
        if (k < s) red[k] += red[k + s];
        __syncthreads();
    }
    float n  = red[0];
    float cs = (ncs + 1e-5f) / (n + 512.0f * 1e-5f) * n;

    for (int d = 0; d < DDIM; d++) {
        int idx = d * KCODES + k;               // coalesced across k
        float nea = embed_avg[idx] * DEC + OMD * g_esum[idx];
        out[OFF_NEA + idx] = nea;
        out[OFF_EN  + idx] = nea / cs;
    }
    if (k == 0) out[OFF_DIFF] = (float)(g_diff * (1.0 / 4194304.0));
}

// ============================================================================
extern "C" void kernel_launch(void* const* d_in, const int* in_sizes, int n_in,
                              void* d_out, int out_size) {
    const float* input        = (const float*)d_in[0];
    const float* embed        = (const float*)d_in[1];
    const float* cluster_size = (const float*)d_in[2];
    const float* embed_avg    = (const float*)d_in[3];
    float* out = (float*)d_out;

    init_kernel<<<128, 256>>>();
    vq_main<<<1024, 256>>>(input, embed, out);
    vq_finalize<<<1, 512>>>(cluster_size, embed_avg, out);
}

// round 9
// speedup vs baseline: 1.3378x; 1.0878x over previous
#include <cuda_runtime.h>
#include <cuda_bf16.h>
#include <float.h>
#include <stdint.h>

#define DDIM   64
#define KCODES 512
#define RB     128
#define NROWS  65536
#define APITCH 400      // bytes/row, 192 bf16 data + pad (4-bank row shift, LDSM conflict-free)
#define BPITCH 400

// -------- output layout (reference tuple, raveled, concatenated, float32) ----
#define OFF_Q    0
#define OFF_DIFF 4194304
#define OFF_IND  4194305
#define OFF_EN   4259841
#define OFF_NCS  4292609
#define OFF_NEA  4293121

// -------- device scratch ----------------------------------------------------
__device__ float  g_esum[DDIM * KCODES];
__device__ float  g_cnt[KCODES];
__device__ float  g_e2[KCODES];
__device__ double g_diff;
__device__ unsigned long long g_ebu[KCODES * 192 / 4];  // bf16 [n][k=192] (3 planes concat)

// -------- dynamic smem layout ------------------------------------------------
#define SM_E2   0                       // f32[512]    2048
#define SM_MIN  2048                    // f32[128]     512
#define SM_IDX  2560                    // i32[128]     512
#define SM_A    3072                    // 128 x APITCH = 51200
#define SM_B    54272                   // 256 x BPITCH = 102400
#define SMEM_TOTAL 156672

__device__ __forceinline__ uint32_t smem_u32(const void* p) {
    uint32_t a;
    asm("{ .reg .u64 t; cvta.to.shared.u64 t, %1; cvt.u32.u64 %0, t; }" : "=r"(a) : "l"(p));
    return a;
}
__device__ __forceinline__ void ldsm_x4(uint32_t* r, uint32_t addr) {
    asm volatile("ldmatrix.sync.aligned.m8n8.x4.shared.b16 {%0,%1,%2,%3}, [%4];"
                 : "=r"(r[0]), "=r"(r[1]), "=r"(r[2]), "=r"(r[3]) : "r"(addr));
}
__device__ __forceinline__ void ldsm_x2(uint32_t* r, uint32_t addr) {
    asm volatile("ldmatrix.sync.aligned.m8n8.x2.shared.b16 {%0,%1}, [%2];"
                 : "=r"(r[0]), "=r"(r[1]) : "r"(addr));
}
#define MMA(C, A, B)                                                               \
    asm volatile("mma.sync.aligned.m16n8k16.row.col.f32.bf16.bf16.f32 "            \
                 "{%0,%1,%2,%3},{%4,%5,%6,%7},{%8,%9},{%0,%1,%2,%3};"              \
                 : "+f"((C)[0]), "+f"((C)[1]), "+f"((C)[2]), "+f"((C)[3])          \
                 : "r"((A)[0]), "r"((A)[1]), "r"((A)[2]), "r"((A)[3]),             \
                   "r"((B)[0]), "r"((B)[1]))

// ============================================================================
// Kernel 0: zero scratch, split embed -> bf16x3 [n][plane*64+d], exact ||e||^2
// ============================================================================
__global__ void prep_kernel(const float* __restrict__ embed) {
    int t = blockIdx.x * blockDim.x + threadIdx.x;
    if (t < DDIM * KCODES) {
        g_esum[t] = 0.0f;
        float x = embed[t];                       // [d][n]
        int d = t >> 9, n = t & 511;
        __nv_bfloat16 b0 = __float2bfloat16(x);
        float r1 = x - __bfloat162float(b0);
        __nv_bfloat16 b1 = __float2bfloat16(r1);
        float r2 = r1 - __bfloat162float(b1);
        __nv_bfloat16 b2 = __float2bfloat16(r2);
        __nv_bfloat16* eb = (__nv_bfloat16*)g_ebu;
        eb[n * 192 +       d] = b0;
        eb[n * 192 +  64 + d] = b1;
        eb[n * 192 + 128 + d] = b2;
    }
    if (t < KCODES) {
        g_cnt[t] = 0.0f;
        float s = 0.0f;
        #pragma unroll 8
        for (int d = 0; d < DDIM; d++) {
            float e = embed[d * KCODES + t];
            s = fmaf(e, e, s);
        }
        g_e2[t] = s;
    }
    if (t == 0) g_diff = 0.0;
}

// ============================================================================
// Kernel 1: HMMA bf16 6-cross-term distance GEMM + argmin + epilogue
//   CTA: 128 rows x 512 codes (2 chunks of 256). warp w owns m-strip w*16.
// ============================================================================
__global__ void vq_main(const float* __restrict__ input,
                        const float* __restrict__ embed,
                        float* __restrict__ out) {
    extern __shared__ char smem[];
    const uint32_t sb = smem_u32(smem);
    float* sE2  = (float*)(smem + SM_E2);
    float* sMin = (float*)(smem + SM_MIN);
    int*   sIdx = (int*)(smem + SM_IDX);

    const int tid = threadIdx.x;
    const int wid = tid >> 5, lane = tid & 31;
    const int r0 = blockIdx.x * RB;

    sE2[tid]       = g_e2[tid];
    sE2[tid + 256] = g_e2[tid + 256];

    // ---- split A (input rows) -> 3 bf16 planes in smem [m][p*64+d], pitch 400 ----
    #pragma unroll
    for (int i = 0; i < 16; i++) {
        int e = tid + 256 * i;                 // 4096 d-pairs
        int m = e >> 5, d0 = (e & 31) * 2;
        float2 v = *(const float2*)&input[(size_t)(r0 + m) * DDIM + d0];
        __nv_bfloat16 p0a = __float2bfloat16(v.x), p0b = __float2bfloat16(v.y);
        float r1a = v.x - __bfloat162float(p0a), r1b = v.y - __bfloat162float(p0b);
        __nv_bfloat16 p1a = __float2bfloat16(r1a), p1b = __float2bfloat16(r1b);
        float r2a = r1a - __bfloat162float(p1a), r2b = r1b - __bfloat162float(p1b);
        __nv_bfloat16 p2a = __float2bfloat16(r2a), p2b = __float2bfloat16(r2b);
        char* row = smem + SM_A + m * APITCH;
        *(uint32_t*)(row +         d0 * 2) = (uint32_t)__bfloat16_as_ushort(p0a) | ((uint32_t)__bfloat16_as_ushort(p0b) << 16);
        *(uint32_t*)(row + 128 +   d0 * 2) = (uint32_t)__bfloat16_as_ushort(p1a) | ((uint32_t)__bfloat16_as_ushort(p1b) << 16);
        *(uint32_t*)(row + 256 +   d0 * 2) = (uint32_t)__bfloat16_as_ushort(p2a) | ((uint32_t)__bfloat16_as_ushort(p2b) << 16);
    }
    __syncthreads();

    // ---- hoist A fragments: plane p, k-step s -> af[p*4+s][4] ----
    uint32_t af[12][4];
    {
        int t4 = lane >> 3, rlo = lane & 7;
        int mrow = wid * 16 + ((t4 & 1) << 3) + rlo;
        int koff = (t4 >> 1) << 3;
        #pragma unroll
        for (int p = 0; p < 3; p++)
            #pragma unroll
            for (int s = 0; s < 4; s++) {
                uint32_t addr = sb + SM_A + mrow * APITCH + (p * 64 + s * 16 + koff) * 2;
                ldsm_x4(af[p * 4 + s], addr);
            }
    }

    // argmin state: row wid*16 + lane/4 (bv0) and +8 (bv1)
    float bv0 = FLT_MAX, bv1 = FLT_MAX;
    int   bk0 = 0x7fffffff, bk1 = 0x7fffffff;

    // 6 cross-terms split into 2 chains of 3
    const int paA[3] = {0, 1, 0}, pbA[3] = {0, 0, 2};
    const int paB[3] = {0, 1, 2}, pbB[3] = {1, 1, 0};

    for (int chunk = 0; chunk < 2; chunk++) {
        // ---- stage B chunk: 256 codes x 192 bf16 (u64 copies, coalesced) ----
        #pragma unroll
        for (int i = 0; i < 48; i++) {
            int u = tid + 256 * i;             // 12288 u64
            int n = u / 48, q = u % 48;
            *(unsigned long long*)(smem + SM_B + n * BPITCH + q * 8) =
                g_ebu[(size_t)(chunk * 256 + n) * 48 + q];
        }
        __syncthreads();

        for (int nt = 0; nt < 32; nt += 2) {
            // ---- B fragments for n-tiles nt, nt+1 ----
            uint32_t bf[2][12][2];
            {
                int rlo = lane & 7, khalf = ((lane >> 3) & 1) << 3;
                #pragma unroll
                for (int u = 0; u < 2; u++)
                    #pragma unroll
                    for (int p = 0; p < 3; p++)
                        #pragma unroll
                        for (int s = 0; s < 4; s++) {
                            uint32_t addr = sb + SM_B + ((nt + u) * 8 + rlo) * BPITCH +
                                            (p * 64 + s * 16 + khalf) * 2;
                            ldsm_x2(bf[u][p * 4 + s], addr);
                        }
            }
            float Cc[2][2][4];
            #pragma unroll
            for (int u = 0; u < 2; u++)
                #pragma unroll
                for (int c = 0; c < 2; c++)
                    #pragma unroll
                    for (int j = 0; j < 4; j++) Cc[u][c][j] = 0.0f;

            // ---- 48 MMAs: 4 independent accumulators, dep distance 4 ----
            #pragma unroll
            for (int i12 = 0; i12 < 12; i12++) {
                int t = i12 >> 2, s = i12 & 3;
                MMA(Cc[0][0], af[paA[t] * 4 + s], bf[0][pbA[t] * 4 + s]);
                MMA(Cc[0][1], af[paB[t] * 4 + s], bf[0][pbB[t] * 4 + s]);
                MMA(Cc[1][0], af[paA[t] * 4 + s], bf[1][pbA[t] * 4 + s]);
                MMA(Cc[1][1], af[paB[t] * 4 + s], bf[1][pbB[t] * 4 + s]);
            }

            // ---- distances + running argmin (ascending n => strict < = first idx) ----
            #pragma unroll
            for (int u = 0; u < 2; u++) {
                int nb = chunk * 256 + (nt + u) * 8 + 2 * (lane & 3);
                float e2a = sE2[nb], e2b = sE2[nb + 1];
                float d00 = e2a - 2.0f * (Cc[u][0][0] + Cc[u][1][0]);
                float d01 = e2b - 2.0f * (Cc[u][0][1] + Cc[u][1][1]);
                float d10 = e2a - 2.0f * (Cc[u][0][2] + Cc[u][1][2]);
                float d11 = e2b - 2.0f * (Cc[u][0][3] + Cc[u][1][3]);
                if (d00 < bv0) { bv0 = d00; bk0 = nb; }
                if (d01 < bv0) { bv0 = d01; bk0 = nb + 1; }
                if (d10 < bv1) { bv1 = d10; bk1 = nb; }
                if (d11 < bv1) { bv1 = d11; bk1 = nb + 1; }
            }
        }
        __syncthreads();   // B readers done before next chunk overwrite
    }

    // ---- reduce argmin across the 4 lanes sharing each row ----
    #pragma unroll
    for (int off = 1; off <= 2; off <<= 1) {
        float ov0 = __shfl_xor_sync(0xffffffffu, bv0, off);
        int   ok0 = __shfl_xor_sync(0xffffffffu, bk0, off);
        float ov1 = __shfl_xor_sync(0xffffffffu, bv1, off);
        int   ok1 = __shfl_xor_sync(0xffffffffu, bk1, off);
        if (ov0 < bv0 || (ov0 == bv0 && ok0 < bk0)) { bv0 = ov0; bk0 = ok0; }
        if (ov1 < bv1 || (ov1 == bv1 && ok1 < bk1)) { bv1 = ov1; bk1 = ok1; }
    }
    if ((lane & 3) == 0) {
        int rq = wid * 16 + (lane >> 2);
        sMin[rq] = bv0; sIdx[rq] = bk0;
        sMin[rq + 8] = bv1; sIdx[rq + 8] = bk1;
    }
    __syncthreads();

    // ---- epilogue: quantize_st, index, scatter, diff (exact fp32) ----
    double dsum = 0.0;
    for (int row = wid; row < RB; row += 8) {
        int kbest = sIdx[row];
        int gr = r0 + row;
        if (lane == 0) {
            out[OFF_IND + gr] = (float)kbest;
            atomicAdd(&g_cnt[kbest], 1.0f);
        }
        #pragma unroll
        for (int h = 0; h < 2; h++) {
            int d = lane + 32 * h;
            float x = input[(size_t)gr * DDIM + d];
            float q = embed[d * KCODES + kbest];
            out[OFF_Q + (size_t)gr * DDIM + d] = x + (q - x);
            float df = q - x;
            dsum += (double)df * (double)df;
            atomicAdd(&g_esum[d * KCODES + kbest], x);
        }
    }
    #pragma unroll
    for (int off = 16; off; off >>= 1)
        dsum += __shfl_xor_sync(0xffffffffu, dsum, off);
    if (lane == 0) atomicAdd(&g_diff, dsum);
}

// ============================================================================
// Kernel 2: EMA update + normalize + diff mean
// ============================================================================
__global__ void vq_finalize(const float* __restrict__ cluster_size,
                            const float* __restrict__ embed_avg,
                            float* __restrict__ out) {
    __shared__ float red[512];
    const int k = threadIdx.x;
    const float DEC = 0.99f;
    const float OMD = (float)(1.0 - 0.99);

    float ncs = cluster_size[k] * DEC + OMD * g_cnt[k];
    out[OFF_NCS + k] = ncs;
    red[k] = ncs;
    __syncthreads();
    for (int s = 256; s; s >>= 1) {
        if (k < s) red[k] += red[k + s];
        __syncthreads();
    }
    float n  = red[0];
    float cs = (ncs + 1e-5f) / (n + 512.0f * 1e-5f) * n;

    for (int d = 0; d < DDIM; d++) {
        int idx = d * KCODES + k;
        float nea = embed_avg[idx] * DEC + OMD * g_esum[idx];
        out[OFF_NEA + idx] = nea;
        out[OFF_EN  + idx] = nea / cs;
    }
    if (k == 0) out[OFF_DIFF] = (float)(g_diff * (1.0 / 4194304.0));
}

// ============================================================================
extern "C" void kernel_launch(void* const* d_in, const int* in_sizes, int n_in,
                              void* d_out, int out_size) {
    const float* input        = (const float*)d_in[0];
    const float* embed        = (const float*)d_in[1];
    const float* cluster_size = (const float*)d_in[2];
    const float* embed_avg    = (const float*)d_in[3];
    float* out = (float*)d_out;

    cudaFuncSetAttribute(vq_main, cudaFuncAttributeMaxDynamicSharedMemorySize, SMEM_TOTAL);
    prep_kernel<<<128, 256>>>(embed);
    vq_main<<<512, 256, SMEM_TOTAL>>>(input, embed, out);
    vq_finalize<<<1, 512>>>(cluster_size, embed_avg, out);
}